// round 1
// baseline (speedup 1.0000x reference)
#include <cuda_runtime.h>
#include <math.h>

// Problem shape (fixed by the dataset)
#define T_LEN   4096
#define D_DIM   1024
#define MAX_B   8
#define C_CHUNKS 32
#define L_CHUNK (T_LEN / C_CHUNKS)   // 128
#define LOG2_L   7                    // L_CHUNK = 2^7

// Scratch: chunk-local end states and chunk carry-in states.
// (device globals — no allocation in kernel_launch, per harness rules)
__device__ float g_Slocal[MAX_B * C_CHUNKS * D_DIM];
__device__ float g_Sin[MAX_B * C_CHUNKS * D_DIM];

// ---------------------------------------------------------------------------
// K1: per-chunk local scan, s_init = 0; store only the chunk-final state.
// grid = (C_CHUNKS, B), block = 256 threads, 4 channels (float4) per thread.
// ---------------------------------------------------------------------------
__global__ __launch_bounds__(256, 4)
void ssm_pass1(const float* __restrict__ x,
               const float* __restrict__ logit_a,
               const float* __restrict__ bvec)
{
    const int j  = blockIdx.x;          // chunk
    const int b  = blockIdx.y;          // batch
    const int dc = threadIdx.x * 4;     // channel base

    const float4 la = *reinterpret_cast<const float4*>(logit_a + dc);
    const float4 bb = *reinterpret_cast<const float4*>(bvec + dc);
    const float ax = tanhf(la.x), ay = tanhf(la.y),
                az = tanhf(la.z), aw = tanhf(la.w);

    float sx = 0.f, sy = 0.f, sz = 0.f, sw = 0.f;

    const float4* xp = reinterpret_cast<const float4*>(
        x + ((size_t)b * T_LEN + (size_t)j * L_CHUNK) * D_DIM + dc);
    const int row4 = D_DIM / 4;

    #pragma unroll 8
    for (int t = 0; t < L_CHUNK; ++t) {
        float4 u = xp[(size_t)t * row4];
        sx = fmaf(ax, sx, bb.x * u.x);
        sy = fmaf(ay, sy, bb.y * u.y);
        sz = fmaf(az, sz, bb.z * u.z);
        sw = fmaf(aw, sw, bb.w * u.w);
    }

    *reinterpret_cast<float4*>(
        g_Slocal + ((size_t)b * C_CHUNKS + j) * D_DIM + dc)
        = make_float4(sx, sy, sz, sw);
}

// ---------------------------------------------------------------------------
// K2: serial carry combine over chunks. One thread per (b, 4 channels).
// carry(0) = 0; carry(j+1) = a^L * carry(j) + Slocal(j).  g_Sin[j] = carry(j).
// ---------------------------------------------------------------------------
__global__ void ssm_carry(const float* __restrict__ logit_a, int B)
{
    const int idx = blockIdx.x * blockDim.x + threadIdx.x;  // over B * D/4
    const int nq  = D_DIM / 4;
    const int b   = idx / nq;
    const int dq  = idx % nq;
    if (b >= B) return;
    const int dc = dq * 4;

    const float4 la = *reinterpret_cast<const float4*>(logit_a + dc);
    float px = tanhf(la.x), py = tanhf(la.y),
          pz = tanhf(la.z), pw = tanhf(la.w);
    // a^L via repeated squaring (L = 2^LOG2_L)
    #pragma unroll
    for (int i = 0; i < LOG2_L; ++i) { px *= px; py *= py; pz *= pz; pw *= pw; }

    float cx = 0.f, cy = 0.f, cz = 0.f, cw = 0.f;
    #pragma unroll
    for (int j = 0; j < C_CHUNKS; ++j) {
        const size_t off = ((size_t)b * C_CHUNKS + j) * D_DIM + dc;
        *reinterpret_cast<float4*>(g_Sin + off) = make_float4(cx, cy, cz, cw);
        const float4 sl = *reinterpret_cast<const float4*>(g_Slocal + off);
        cx = fmaf(px, cx, sl.x);
        cy = fmaf(py, cy, sl.y);
        cz = fmaf(pz, cz, sl.z);
        cw = fmaf(pw, cw, sl.w);
    }
}

// ---------------------------------------------------------------------------
// K3: final pass. Seed s with the true carry-in, recompute local scan, emit y.
// ---------------------------------------------------------------------------
__global__ __launch_bounds__(256, 4)
void ssm_pass2(const float* __restrict__ x,
               const float* __restrict__ logit_a,
               const float* __restrict__ bvec,
               const float* __restrict__ cvec,
               const float* __restrict__ dvec,
               float* __restrict__ y)
{
    const int j  = blockIdx.x;
    const int b  = blockIdx.y;
    const int dc = threadIdx.x * 4;

    const float4 la = *reinterpret_cast<const float4*>(logit_a + dc);
    const float4 bb = *reinterpret_cast<const float4*>(bvec + dc);
    const float4 cc = *reinterpret_cast<const float4*>(cvec + dc);
    const float4 dd = *reinterpret_cast<const float4*>(dvec + dc);
    const float ax = tanhf(la.x), ay = tanhf(la.y),
                az = tanhf(la.z), aw = tanhf(la.w);

    const float4 s0 = *reinterpret_cast<const float4*>(
        g_Sin + ((size_t)b * C_CHUNKS + j) * D_DIM + dc);
    float sx = s0.x, sy = s0.y, sz = s0.z, sw = s0.w;

    const size_t base = ((size_t)b * T_LEN + (size_t)j * L_CHUNK) * D_DIM + dc;
    const float4* xp = reinterpret_cast<const float4*>(x + base);
    float4*       yp = reinterpret_cast<float4*>(y + base);
    const int row4 = D_DIM / 4;

    #pragma unroll 8
    for (int t = 0; t < L_CHUNK; ++t) {
        float4 u = xp[(size_t)t * row4];
        sx = fmaf(ax, sx, bb.x * u.x);
        sy = fmaf(ay, sy, bb.y * u.y);
        sz = fmaf(az, sz, bb.z * u.z);
        sw = fmaf(aw, sw, bb.w * u.w);
        float4 o;
        o.x = fmaf(cc.x, sx, dd.x * u.x);
        o.y = fmaf(cc.y, sy, dd.y * u.y);
        o.z = fmaf(cc.z, sz, dd.z * u.z);
        o.w = fmaf(cc.w, sw, dd.w * u.w);
        yp[(size_t)t * row4] = o;
    }
}

// ---------------------------------------------------------------------------
// Launch: inputs in metadata order: x, logit_a, b, c, d. Output fp32 (B,T,D).
// ---------------------------------------------------------------------------
extern "C" void kernel_launch(void* const* d_in, const int* in_sizes, int n_in,
                              void* d_out, int out_size)
{
    const float* x  = (const float*)d_in[0];
    const float* la = (const float*)d_in[1];
    const float* bv = (const float*)d_in[2];
    const float* cv = (const float*)d_in[3];
    const float* dv = (const float*)d_in[4];
    float* y = (float*)d_out;

    const int B = in_sizes[0] / (T_LEN * D_DIM);   // = 8

    dim3 grid(C_CHUNKS, B);
    dim3 blk(256);

    ssm_pass1<<<grid, blk>>>(x, la, bv);

    const int carry_threads = B * (D_DIM / 4);     // 2048
    ssm_carry<<<(carry_threads + 255) / 256, 256>>>(la, B);

    ssm_pass2<<<grid, blk>>>(x, la, bv, cv, dv, y);
}